// round 14
// baseline (speedup 1.0000x reference)
#include <cuda_runtime.h>
#include <math.h>

#define NN 20000
#define EE 640000
#define EPAD 800000        // CSR capacity, rows padded to multiples of 8
#define GGR 64
#define HH 128
#define EIN 32
#define NSB ((NN + 255) / 256) // 79 scan blocks
#define NT64 ((NN + 63) / 64)  // 313 conv tiles
#define CONV_GRID 296
#define CONV_SMEM ((HH*HH + 64*HH)*4)   // 64KB M + 32KB X = 96KB dynamic

// ---------------- scratch (static device globals; no allocation) ----------------
__device__ float g_hA[(NN+1)*HH];   // row NN = zero sentinel
__device__ float g_hB[(NN+1)*HH];   // row NN = zero sentinel
__device__ float g_D1[NN*HH];
__device__ float g_D2[NN*HH];
__device__ float g_S[NN*EIN];
__device__ int   g_deg[NN];
__device__ int   g_rowptr[NN+1];    // padded exclusive scan
__device__ int   g_fill[NN];
__device__ int2  g_csr[EPAD];       // .x = src node (NN = sentinel), .y = edge id
__device__ int   g_tmp[NN];
__device__ int   g_bsum[NSB];
__device__ int   g_boff[NSB];
__device__ int   g_ctr[8];          // dynamic tile counters (one per conv launch)
__device__ float g_M1[HH*HH], g_M2[HH*HH];
__device__ float g_T1[EIN*HH], g_T2[EIN*HH];
__device__ float g_Gm1[EIN*HH], g_Gm2[EIN*HH];
__device__ float g_w1[HH], g_w2[HH];
__device__ float g_u1[HH], g_u2[HH];
__device__ float g_v1[HH], g_v2[HH];
__device__ float g_psum[GGR*HH];
__device__ float g_pmax[GGR*HH];
__device__ int   g_cnt[GGR];

#define F4ACC(a,b) { (a).x+=(b).x; (a).y+=(b).y; (a).z+=(b).z; (a).w+=(b).w; }
#define F4FMA(a,s,m) { (a).x+=(s)*(m).x; (a).y+=(s)*(m).y; (a).z+=(s)*(m).z; (a).w+=(s)*(m).w; }

// ---------------- init ----------------
__global__ void init_zero() {
    int i = blockIdx.x*blockDim.x + threadIdx.x;
    int stride = gridDim.x*blockDim.x;
    for (int k=i; k<NN; k+=stride) g_deg[k]=0;
    for (int k=i; k<GGR*HH; k+=stride){ g_psum[k]=0.f; g_pmax[k]=0.f; }
    for (int k=i; k<GGR; k+=stride) g_cnt[k]=0;
    for (int k=i; k<HH; k+=stride){ g_hA[NN*HH+k]=0.f; g_hB[NN*HH+k]=0.f; }
    if (i < 8) g_ctr[i] = 0;
}

// ---------------- CSR build ----------------
__global__ void deg_kernel(const int* __restrict__ dst) {
    int e = blockIdx.x*blockDim.x + threadIdx.x;
    if (e < EE) atomicAdd(&g_deg[dst[e]], 1);
}

// 3-phase scan of padded degrees
__global__ void scan1_kernel() {
    __shared__ int ws[8];
    int b = blockIdx.x, t = threadIdx.x;
    int i = b*256 + t;
    int v = (i < NN) ? ((g_deg[i] + 7) & ~7) : 0;
    int x = v;
    #pragma unroll
    for (int o=1;o<32;o<<=1){ int y=__shfl_up_sync(0xFFFFFFFFu,x,o); if ((t&31)>=o) x+=y; }
    if ((t&31)==31) ws[t>>5]=x;
    __syncthreads();
    if (t < 8) {
        int s = ws[t];
        #pragma unroll
        for (int o=1;o<8;o<<=1){ int y=__shfl_up_sync(0xFFu,s,o); if (t>=o) s+=y; }
        ws[t] = s;
    }
    __syncthreads();
    int add = (t>=32) ? ws[(t>>5)-1] : 0;
    int incl = x + add;
    if (i < NN) g_tmp[i] = incl;
    if (t == 255) g_bsum[b] = incl;
}

__global__ void scan2_kernel() {
    __shared__ int ws[4];
    int t = threadIdx.x;
    int v = (t < NSB) ? g_bsum[t] : 0;
    int x = v;
    #pragma unroll
    for (int o=1;o<32;o<<=1){ int y=__shfl_up_sync(0xFFFFFFFFu,x,o); if ((t&31)>=o) x+=y; }
    if ((t&31)==31) ws[t>>5]=x;
    __syncthreads();
    int add = 0;
    if (t>=32) add = ws[0];
    if (t>=64) add += ws[1];
    if (t>=96) add += ws[2];
    if (t < NSB) g_boff[t] = x + add - v;
}

__global__ void scan3_kernel() {
    int i = blockIdx.x*256 + threadIdx.x;
    if (i < NN) {
        int v = (g_deg[i] + 7) & ~7;
        int excl = g_boff[blockIdx.x] + g_tmp[i] - v;
        g_rowptr[i] = excl;
        g_fill[i]   = excl;
        if (i == NN-1) g_rowptr[NN] = excl + v;
    }
}

__global__ void fill_kernel(const int* __restrict__ src, const int* __restrict__ dst) {
    int e = blockIdx.x*blockDim.x + threadIdx.x;
    if (e < EE) {
        int d = dst[e];
        int pos = atomicAdd(&g_fill[d], 1);
        g_csr[pos] = make_int2(src[e], e);
    }
}

// write sentinel entries only into each row's padding region
__global__ void pad_kernel() {
    int i = blockIdx.x*blockDim.x + threadIdx.x;
    if (i < NN) {
        int p = g_fill[i];            // rowptr[i] + deg[i]
        int end = g_rowptr[i+1];
        int2 s = make_int2(NN, 0);
        for (; p < end; p++) g_csr[p] = s;
    }
}

// S[i,:] = sum of edge_attr over real incoming edges (warp per node, lane = channel)
__global__ void S_kernel(const float* __restrict__ edge_attr) {
    int gw   = (blockIdx.x*blockDim.x + threadIdx.x) >> 5;
    int lane = threadIdx.x & 31;
    if (gw >= NN) return;
    int s = g_rowptr[gw], d = g_deg[gw];
    float a0=0.f, a1=0.f, a2=0.f, a3=0.f;
    int p = s;
    for (; p + 4 <= s + d; p += 4) {
        int e0 = g_csr[p].y, e1 = g_csr[p+1].y, e2 = g_csr[p+2].y, e3 = g_csr[p+3].y;
        a0 += edge_attr[e0*EIN + lane];
        a1 += edge_attr[e1*EIN + lane];
        a2 += edge_attr[e2*EIN + lane];
        a3 += edge_attr[e3*EIN + lane];
    }
    for (; p < s + d; p++) a0 += edge_attr[g_csr[p].y*EIN + lane];
    g_S[gw*EIN + lane] = (a0+a1)+(a2+a3);
}

// ---------------- tiny weight-product precompute ----------------
__global__ void tinyA(const float* __restrict__ Wn, const float* __restrict__ Wu,
                      const float* __restrict__ We, const float* __restrict__ We2l,
                      const float* __restrict__ be2l, const float* __restrict__ be,
                      const float* __restrict__ bn, int X) {
    int c = threadIdx.x, b = blockIdx.x;
    float* M = X ? g_M2 : g_M1;
    float* T = X ? g_T2 : g_T1;
    float* w = X ? g_w2 : g_w1;
    if (b < 128) {
        float a = 0.f;
        #pragma unroll 8
        for (int k=0;k<128;k++) a += Wn[b*128+k]*Wu[k*128+c];
        M[b*128+c] = a;
    } else if (b < 160) {
        int r = b - 128;
        float a = 0.f;
        #pragma unroll 8
        for (int k=0;k<128;k++) a += We2l[r*128+k]*We[k*128+c];
        T[r*128+c] = a;
    } else {
        float a = be[c] + bn[c];
        #pragma unroll 8
        for (int k=0;k<128;k++) a += be2l[k]*We[k*128+c];
        w[c] = a;
    }
}

__global__ void tinyB(const float* __restrict__ Wu, const float* __restrict__ bn,
                      const float* __restrict__ be, const float* __restrict__ bu, int X) {
    int c = threadIdx.x, b = blockIdx.x;
    const float* T = X ? g_T2 : g_T1;
    const float* w = X ? g_w2 : g_w1;
    float* Gm = X ? g_Gm2 : g_Gm1;
    float* u  = X ? g_u2  : g_u1;
    float* v  = X ? g_v2  : g_v1;
    if (b < 32) {
        float a = 0.f;
        #pragma unroll 8
        for (int k=0;k<128;k++) a += T[b*128+k]*Wu[k*128+c];
        Gm[b*128+c] = a;
    } else if (b == 32) {
        float a = 0.f;
        #pragma unroll 8
        for (int k=0;k<128;k++) a += w[k]*Wu[k*128+c];
        u[c] = a;
    } else {
        float a = bu[c];
        #pragma unroll 8
        for (int k=0;k<128;k++) a += (bn[k]+be[k])*Wu[k*128+c];
        v[c] = a;
    }
}

// D_X[i,:] = S[i,:] @ G_X + deg[i]*u_X + v_X
__global__ void D_kernel() {
    __shared__ float G1s[EIN*HH];
    __shared__ float G2s[EIN*HH];
    __shared__ float Ssh[EIN];
    int c = threadIdx.x;
    for (int k=c; k<EIN*HH; k+=128) { G1s[k]=g_Gm1[k]; G2s[k]=g_Gm2[k]; }
    float u1=g_u1[c], u2=g_u2[c], v1=g_v1[c], v2=g_v2[c];
    __syncthreads();
    for (int i=blockIdx.x; i<NN; i+=gridDim.x) {
        if (c<EIN) Ssh[c] = g_S[i*EIN+c];
        __syncthreads();
        float dg = (float)g_deg[i];
        float a1 = v1 + dg*u1, a2 = v2 + dg*u2;
        #pragma unroll
        for (int k=0;k<EIN;k++){ float s=Ssh[k]; a1 += s*G1s[k*HH+c]; a2 += s*G2s[k*HH+c]; }
        g_D1[i*HH+c] = a1;
        g_D2[i*HH+c] = a2;
        __syncthreads();
    }
}

// ---------------- fused conv: hout = [relu]( ((A+I)hin) @ M + D/bias ) ----------------
// persistent, 256 thr, 2 blocks/SM, dynamic tiles of 64 rows.
// Phase 1 (all 8 warps): gather (A+I)h rows directly into Xs smem.
// Phase 2 (all 8 warps): GEMM Xs @ Ms + D, relu, store.
// Chip-level overlap: the sibling block on each SM is in the opposite phase.
template<bool PROJ>
__global__ void __launch_bounds__(256, 2)
conv_fused(const float* __restrict__ xin, const float* __restrict__ Mext,
           const float* __restrict__ bias, int which, int dstA, int slot)
{
    extern __shared__ float smem[];
    float* Ms = smem;              // [128][128]
    float* Xs = smem + HH*HH;      // [64][128]
    __shared__ int s_tile;

    const float* M   = PROJ ? Mext : (which ? g_M2 : g_M1);
    const float* hin = PROJ ? xin  : (dstA ? g_hB : g_hA);
    const float* D   = which ? g_D2 : g_D1;
    float* hout = dstA ? g_hA : g_hB;

    int tid = threadIdx.x;
    for (int i = tid; i < HH*HH/4; i += 256)
        ((float4*)Ms)[i] = ((const float4*)M)[i];

    int lane = tid & 31, wid = tid >> 5;
    int colb = lane * 4;           // GEMM: col group (4 cols)
    int rb = wid * 8;              // GEMM: row group (8 rows)
    float4 zero = make_float4(0.f,0.f,0.f,0.f);

    float4 cbias = zero;
    if (PROJ) cbias = *(const float4*)(bias + colb);

    for (;;) {
        __syncthreads();     // protect prev-iter Xs reads + s_tile (also first-pass Ms)
        if (tid == 0) s_tile = atomicAdd(&g_ctr[slot], 1);
        __syncthreads();
        int tile = s_tile;
        if (tile >= NT64) break;
        int row0 = tile * 64;

        // -------- phase 1: gather (A+I)h rows into Xs (warp per row, lane = 4 channels)
        for (int n = wid; n < 64; n += 8) {
            int i = row0 + n;
            float4 a0=zero,a1=zero,a2=zero,a3=zero,a4=zero,a5=zero,a6=zero,a7=zero;
            if (i < NN) {
                const float* hl = hin + lane*4;
                a0 = *(const float4*)(hl + i*HH);
                if (!PROJ) {
                    int s = g_rowptr[i], e = g_rowptr[i+1];
                    for (int p = s; p < e; p += 8) {
                        const int4* cp = (const int4*)(g_csr + p);  // 8 int2 entries
                        int4 c0 = cp[0], c1 = cp[1], c2 = cp[2], c3 = cp[3];
                        float4 b0 = *(const float4*)(hl + c0.x*HH);
                        float4 b1 = *(const float4*)(hl + c0.z*HH);
                        float4 b2 = *(const float4*)(hl + c1.x*HH);
                        float4 b3 = *(const float4*)(hl + c1.z*HH);
                        float4 b4 = *(const float4*)(hl + c2.x*HH);
                        float4 b5 = *(const float4*)(hl + c2.z*HH);
                        float4 b6 = *(const float4*)(hl + c3.x*HH);
                        float4 b7 = *(const float4*)(hl + c3.z*HH);
                        F4ACC(a0,b0); F4ACC(a1,b1); F4ACC(a2,b2); F4ACC(a3,b3);
                        F4ACC(a4,b4); F4ACC(a5,b5); F4ACC(a6,b6); F4ACC(a7,b7);
                    }
                }
            }
            F4ACC(a0,a1); F4ACC(a2,a3); F4ACC(a4,a5); F4ACC(a6,a7);
            F4ACC(a0,a2); F4ACC(a4,a6); F4ACC(a0,a4);
            *(float4*)(Xs + n*HH + lane*4) = a0;
        }

        // acc init from D / bias (global loads, overlap gather tail)
        float4 acc[8];
        if (PROJ) {
            #pragma unroll
            for (int r=0;r<8;r++) acc[r] = cbias;
        } else {
            #pragma unroll
            for (int r=0;r<8;r++) {
                int gi = row0 + rb + r;
                acc[r] = (gi < NN) ? *(const float4*)(D + gi*HH + colb) : zero;
            }
        }
        __syncthreads();

        // -------- phase 2: GEMM Xs @ Ms (+acc), thread = 8 rows x 4 cols
        const float* G = Xs + rb*HH;
        #pragma unroll 2
        for (int k0 = 0; k0 < HH; k0 += 4) {
            float4 m0 = *(const float4*)(Ms + (k0+0)*HH + colb);
            float4 m1 = *(const float4*)(Ms + (k0+1)*HH + colb);
            float4 m2 = *(const float4*)(Ms + (k0+2)*HH + colb);
            float4 m3 = *(const float4*)(Ms + (k0+3)*HH + colb);
            #pragma unroll
            for (int r=0;r<8;r++) {
                float4 g = *(const float4*)(G + r*HH + k0);   // broadcast within warp
                F4FMA(acc[r], g.x, m0);
                F4FMA(acc[r], g.y, m1);
                F4FMA(acc[r], g.z, m2);
                F4FMA(acc[r], g.w, m3);
            }
        }
        #pragma unroll
        for (int r=0;r<8;r++) {
            int gi = row0 + rb + r;
            if (gi < NN) {
                float4 o = acc[r];
                if (!PROJ) {
                    o.x=fmaxf(o.x,0.f); o.y=fmaxf(o.y,0.f);
                    o.z=fmaxf(o.z,0.f); o.w=fmaxf(o.w,0.f);
                }
                *(float4*)(hout + gi*HH + colb) = o;
            }
        }
    }
}

// ---------------- pooling (batch sorted -> run-based partial reduce) ----------------
__global__ void pool_kernel(const int* __restrict__ batch) {
    __shared__ int bsh[128];
    int c = threadIdx.x;
    int s = blockIdx.x*128;
    int nloc = NN - s; if (nloc > 128) nloc = 128;
    for (int i=c; i<nloc; i+=128) bsh[i] = batch[s+i];
    __syncthreads();
    const float* h = g_hA;
    float sum=0.f, mx=0.f; int cnt=0;
    int cur = bsh[0];
    for (int i=0;i<nloc;i++) {
        int g = bsh[i];
        if (g != cur) {
            atomicAdd(&g_psum[cur*HH+c], sum);
            atomicMax((unsigned int*)&g_pmax[cur*HH+c], __float_as_uint(mx));
            if (c==0) atomicAdd(&g_cnt[cur], cnt);
            cur=g; sum=0.f; mx=0.f; cnt=0;
        }
        float v = h[(s+i)*HH + c];
        sum += v; mx = fmaxf(mx, v); cnt++;
    }
    atomicAdd(&g_psum[cur*HH+c], sum);
    atomicMax((unsigned int*)&g_pmax[cur*HH+c], __float_as_uint(mx));
    if (c==0) atomicAdd(&g_cnt[cur], cnt);
}

// ---------------- readout head ----------------
__global__ void head_kernel(const float* __restrict__ Wm1, const float* __restrict__ bm1,
                            const float* __restrict__ Wm2, const float* __restrict__ bm2,
                            float* __restrict__ out) {
    __shared__ float pooled[2*HH];
    __shared__ float z1[HH];
    int g = blockIdx.x, c = threadIdx.x;
    float denom = fmaxf((float)g_cnt[g], 1.f);
    pooled[c]    = g_psum[g*HH+c] / denom;
    pooled[HH+c] = g_pmax[g*HH+c];
    __syncthreads();
    float a = bm1[c];
    #pragma unroll 8
    for (int k=0;k<2*HH;k++) a += pooled[k]*Wm1[k*HH+c];
    z1[c] = fmaxf(a, 0.f);
    __syncthreads();
    if (c < 2) {
        float o = bm2[c];
        for (int k=0;k<HH;k++) o += z1[k]*Wm2[k*2+c];
        out[g*2+c] = 1.f/(1.f+expf(-o));
    }
}

// ---------------- launch ----------------
extern "C" void kernel_launch(void* const* d_in, const int* in_sizes, int n_in,
                              void* d_out, int out_size) {
    const float* x         = (const float*)d_in[0];
    const float* edge_attr = (const float*)d_in[1];
    const int*   ei        = (const int*)  d_in[2];
    const int*   batch     = (const int*)  d_in[3];
    const float* Wn2l = (const float*)d_in[4];
    const float* bn2l = (const float*)d_in[5];
    const float* We2l = (const float*)d_in[6];
    const float* be2l = (const float*)d_in[7];
    const float* Wn1  = (const float*)d_in[8];
    const float* bn1  = (const float*)d_in[9];
    const float* We1  = (const float*)d_in[10];
    const float* be1  = (const float*)d_in[11];
    const float* Wu1  = (const float*)d_in[12];
    const float* bu1  = (const float*)d_in[13];
    const float* Wn2  = (const float*)d_in[14];
    const float* bn2  = (const float*)d_in[15];
    const float* We2  = (const float*)d_in[16];
    const float* be2  = (const float*)d_in[17];
    const float* Wu2  = (const float*)d_in[18];
    const float* bu2  = (const float*)d_in[19];
    const float* Wm1  = (const float*)d_in[20];
    const float* bm1  = (const float*)d_in[21];
    const float* Wm2  = (const float*)d_in[22];
    const float* bm2  = (const float*)d_in[23];
    float* out = (float*)d_out;

    const int* src = ei;
    const int* dst = ei + EE;

    cudaFuncSetAttribute(conv_fused<true>,  cudaFuncAttributeMaxDynamicSharedMemorySize, CONV_SMEM);
    cudaFuncSetAttribute(conv_fused<false>, cudaFuncAttributeMaxDynamicSharedMemorySize, CONV_SMEM);

    init_zero<<<160, 256>>>();
    deg_kernel<<<(EE+255)/256, 256>>>(dst);
    scan1_kernel<<<NSB, 256>>>();
    // h0 = x @ Wn2l + bn2l -> g_hA (independent of CSR), slot 0
    conv_fused<true><<<CONV_GRID, 256, CONV_SMEM>>>(x, Wn2l, bn2l, 0, /*dstA=*/1, 0);
    scan2_kernel<<<1, 128>>>();
    scan3_kernel<<<NSB, 256>>>();
    fill_kernel<<<(EE+255)/256, 256>>>(src, dst);
    pad_kernel<<<(NN+255)/256, 256>>>();
    S_kernel<<<(NN*32)/256, 256>>>(edge_attr);

    tinyA<<<161, 128>>>(Wn1, Wu1, We1, We2l, be2l, be1, bn1, 0);
    tinyA<<<161, 128>>>(Wn2, Wu2, We2, We2l, be2l, be2, bn2, 1);
    tinyB<<<34, 128>>>(Wu1, bn1, be1, bu1, 0);
    tinyB<<<34, 128>>>(Wu2, bn2, be2, bu2, 1);
    D_kernel<<<296, 128>>>();

    // 3 x (conv1, conv2): fused gather+GEMM, ping-pong A<->B, end in A; slots 1..6
    conv_fused<false><<<CONV_GRID, 256, CONV_SMEM>>>(nullptr, nullptr, nullptr, 0, 0, 1); // A->B
    conv_fused<false><<<CONV_GRID, 256, CONV_SMEM>>>(nullptr, nullptr, nullptr, 1, 1, 2); // B->A
    conv_fused<false><<<CONV_GRID, 256, CONV_SMEM>>>(nullptr, nullptr, nullptr, 0, 0, 3);
    conv_fused<false><<<CONV_GRID, 256, CONV_SMEM>>>(nullptr, nullptr, nullptr, 1, 1, 4);
    conv_fused<false><<<CONV_GRID, 256, CONV_SMEM>>>(nullptr, nullptr, nullptr, 0, 0, 5);
    conv_fused<false><<<CONV_GRID, 256, CONV_SMEM>>>(nullptr, nullptr, nullptr, 1, 1, 6);

    pool_kernel<<<(NN+127)/128, 128>>>(batch);
    head_kernel<<<GGR, 128>>>(Wm1, bm1, Wm2, bm2, out);
}

// round 16
// speedup vs baseline: 1.1146x; 1.1146x over previous
#include <cuda_runtime.h>
#include <math.h>

#define NN 20000
#define EE 640000
#define EPAD 800000        // CSR capacity, rows padded to multiples of 8
#define GGR 64
#define HH 128
#define EIN 32
#define NSB ((NN + 255) / 256) // 79 scan blocks
#define NT32 ((NN + 31) / 32)  // 625 gemm tiles
#define GEMM_GRID 296
#define GEMM_SMEM ((HH*HH + 2*32*HH)*4)   // 64KB M + 2x16KB X = 96KB dynamic

// ---------------- scratch (static device globals; no allocation) ----------------
__device__ float g_hA[(NN+1)*HH];   // h lives here; row NN = zero sentinel
__device__ float g_hB[NN*HH];       // X = (A+I)h scratch
__device__ float g_D1[NN*HH];
__device__ float g_D2[NN*HH];
__device__ float g_S[NN*EIN];
__device__ int   g_deg[NN];
__device__ int   g_rowptr[NN+1];    // padded exclusive scan
__device__ int   g_fill[NN];
__device__ int2  g_csr[EPAD];       // .x = src node (NN = sentinel), .y = edge id
__device__ int   g_tmp[NN];
__device__ int   g_bsum[NSB];
__device__ int   g_boff[NSB];
__device__ int   g_ctr[8];          // dynamic tile counters (one per gemm launch)
__device__ float g_M1[HH*HH], g_M2[HH*HH];
__device__ float g_T1[EIN*HH], g_T2[EIN*HH];
__device__ float g_Gm1[EIN*HH], g_Gm2[EIN*HH];
__device__ float g_w1[HH], g_w2[HH];
__device__ float g_u1[HH], g_u2[HH];
__device__ float g_v1[HH], g_v2[HH];
__device__ float g_psum[GGR*HH];
__device__ float g_pmax[GGR*HH];
__device__ int   g_cnt[GGR];

#define F4ACC(a,b) { (a).x+=(b).x; (a).y+=(b).y; (a).z+=(b).z; (a).w+=(b).w; }
#define F4FMA(a,s,m) { (a).x+=(s)*(m).x; (a).y+=(s)*(m).y; (a).z+=(s)*(m).z; (a).w+=(s)*(m).w; }

// ---------------- init ----------------
__global__ void init_zero() {
    int i = blockIdx.x*blockDim.x + threadIdx.x;
    int stride = gridDim.x*blockDim.x;
    for (int k=i; k<NN; k+=stride) g_deg[k]=0;
    for (int k=i; k<GGR*HH; k+=stride){ g_psum[k]=0.f; g_pmax[k]=0.f; }
    for (int k=i; k<GGR; k+=stride) g_cnt[k]=0;
    for (int k=i; k<HH; k+=stride) g_hA[NN*HH+k]=0.f;
    if (i < 8) g_ctr[i] = 0;
}

// ---------------- CSR build ----------------
__global__ void deg_kernel(const int* __restrict__ dst) {
    int e = blockIdx.x*blockDim.x + threadIdx.x;
    if (e < EE) atomicAdd(&g_deg[dst[e]], 1);
}

// 3-phase scan of padded degrees
__global__ void scan1_kernel() {
    __shared__ int ws[8];
    int b = blockIdx.x, t = threadIdx.x;
    int i = b*256 + t;
    int v = (i < NN) ? ((g_deg[i] + 7) & ~7) : 0;
    int x = v;
    #pragma unroll
    for (int o=1;o<32;o<<=1){ int y=__shfl_up_sync(0xFFFFFFFFu,x,o); if ((t&31)>=o) x+=y; }
    if ((t&31)==31) ws[t>>5]=x;
    __syncthreads();
    if (t < 8) {
        int s = ws[t];
        #pragma unroll
        for (int o=1;o<8;o<<=1){ int y=__shfl_up_sync(0xFFu,s,o); if (t>=o) s+=y; }
        ws[t] = s;
    }
    __syncthreads();
    int add = (t>=32) ? ws[(t>>5)-1] : 0;
    int incl = x + add;
    if (i < NN) g_tmp[i] = incl;
    if (t == 255) g_bsum[b] = incl;
}

__global__ void scan2_kernel() {
    __shared__ int ws[4];
    int t = threadIdx.x;
    int v = (t < NSB) ? g_bsum[t] : 0;
    int x = v;
    #pragma unroll
    for (int o=1;o<32;o<<=1){ int y=__shfl_up_sync(0xFFFFFFFFu,x,o); if ((t&31)>=o) x+=y; }
    if ((t&31)==31) ws[t>>5]=x;
    __syncthreads();
    int add = 0;
    if (t>=32) add = ws[0];
    if (t>=64) add += ws[1];
    if (t>=96) add += ws[2];
    if (t < NSB) g_boff[t] = x + add - v;
}

__global__ void scan3_kernel() {
    int i = blockIdx.x*256 + threadIdx.x;
    if (i < NN) {
        int v = (g_deg[i] + 7) & ~7;
        int excl = g_boff[blockIdx.x] + g_tmp[i] - v;
        g_rowptr[i] = excl;
        g_fill[i]   = excl;
        if (i == NN-1) g_rowptr[NN] = excl + v;
    }
}

__global__ void fill_kernel(const int* __restrict__ src, const int* __restrict__ dst) {
    int e = blockIdx.x*blockDim.x + threadIdx.x;
    if (e < EE) {
        int d = dst[e];
        int pos = atomicAdd(&g_fill[d], 1);
        g_csr[pos] = make_int2(src[e], e);
    }
}

// write sentinel entries only into each row's padding region
__global__ void pad_kernel() {
    int i = blockIdx.x*blockDim.x + threadIdx.x;
    if (i < NN) {
        int p = g_fill[i];            // rowptr[i] + deg[i]
        int end = g_rowptr[i+1];
        int2 s = make_int2(NN, 0);
        for (; p < end; p++) g_csr[p] = s;
    }
}

// S[i,:] = sum of edge_attr over real incoming edges (warp per node, lane = channel)
__global__ void S_kernel(const float* __restrict__ edge_attr) {
    int gw   = (blockIdx.x*blockDim.x + threadIdx.x) >> 5;
    int lane = threadIdx.x & 31;
    if (gw >= NN) return;
    int s = g_rowptr[gw], d = g_deg[gw];
    float a0=0.f, a1=0.f, a2=0.f, a3=0.f;
    int p = s;
    for (; p + 4 <= s + d; p += 4) {
        int e0 = g_csr[p].y, e1 = g_csr[p+1].y, e2 = g_csr[p+2].y, e3 = g_csr[p+3].y;
        a0 += edge_attr[e0*EIN + lane];
        a1 += edge_attr[e1*EIN + lane];
        a2 += edge_attr[e2*EIN + lane];
        a3 += edge_attr[e3*EIN + lane];
    }
    for (; p < s + d; p++) a0 += edge_attr[g_csr[p].y*EIN + lane];
    g_S[gw*EIN + lane] = (a0+a1)+(a2+a3);
}

// ---------------- tiny weight-product precompute ----------------
__global__ void tinyA(const float* __restrict__ Wn, const float* __restrict__ Wu,
                      const float* __restrict__ We, const float* __restrict__ We2l,
                      const float* __restrict__ be2l, const float* __restrict__ be,
                      const float* __restrict__ bn, int X) {
    int c = threadIdx.x, b = blockIdx.x;
    float* M = X ? g_M2 : g_M1;
    float* T = X ? g_T2 : g_T1;
    float* w = X ? g_w2 : g_w1;
    if (b < 128) {
        float a = 0.f;
        #pragma unroll 8
        for (int k=0;k<128;k++) a += Wn[b*128+k]*Wu[k*128+c];
        M[b*128+c] = a;
    } else if (b < 160) {
        int r = b - 128;
        float a = 0.f;
        #pragma unroll 8
        for (int k=0;k<128;k++) a += We2l[r*128+k]*We[k*128+c];
        T[r*128+c] = a;
    } else {
        float a = be[c] + bn[c];
        #pragma unroll 8
        for (int k=0;k<128;k++) a += be2l[k]*We[k*128+c];
        w[c] = a;
    }
}

__global__ void tinyB(const float* __restrict__ Wu, const float* __restrict__ bn,
                      const float* __restrict__ be, const float* __restrict__ bu, int X) {
    int c = threadIdx.x, b = blockIdx.x;
    const float* T = X ? g_T2 : g_T1;
    const float* w = X ? g_w2 : g_w1;
    float* Gm = X ? g_Gm2 : g_Gm1;
    float* u  = X ? g_u2  : g_u1;
    float* v  = X ? g_v2  : g_v1;
    if (b < 32) {
        float a = 0.f;
        #pragma unroll 8
        for (int k=0;k<128;k++) a += T[b*128+k]*Wu[k*128+c];
        Gm[b*128+c] = a;
    } else if (b == 32) {
        float a = 0.f;
        #pragma unroll 8
        for (int k=0;k<128;k++) a += w[k]*Wu[k*128+c];
        u[c] = a;
    } else {
        float a = bu[c];
        #pragma unroll 8
        for (int k=0;k<128;k++) a += (bn[k]+be[k])*Wu[k*128+c];
        v[c] = a;
    }
}

// D_X[i,:] = S[i,:] @ G_X + deg[i]*u_X + v_X
__global__ void D_kernel() {
    __shared__ float G1s[EIN*HH];
    __shared__ float G2s[EIN*HH];
    __shared__ float Ssh[EIN];
    int c = threadIdx.x;
    for (int k=c; k<EIN*HH; k+=128) { G1s[k]=g_Gm1[k]; G2s[k]=g_Gm2[k]; }
    float u1=g_u1[c], u2=g_u2[c], v1=g_v1[c], v2=g_v2[c];
    __syncthreads();
    for (int i=blockIdx.x; i<NN; i+=gridDim.x) {
        if (c<EIN) Ssh[c] = g_S[i*EIN+c];
        __syncthreads();
        float dg = (float)g_deg[i];
        float a1 = v1 + dg*u1, a2 = v2 + dg*u2;
        #pragma unroll
        for (int k=0;k<EIN;k++){ float s=Ssh[k]; a1 += s*G1s[k*HH+c]; a2 += s*G2s[k*HH+c]; }
        g_D1[i*HH+c] = a1;
        g_D2[i*HH+c] = a2;
        __syncthreads();
    }
}

// ---------------- aggregation: X = (A+I) h  (g_hA -> g_hB) ----------------
// warp per node, lane owns 4 channels, MLP-8 over padded CSR (int2 entries)
__global__ void agg_kernel() {
    int gw   = (blockIdx.x*blockDim.x + threadIdx.x) >> 5;
    int lane = threadIdx.x & 31;
    if (gw >= NN) return;
    const float* hl = g_hA + lane*4;
    float4 z = make_float4(0.f,0.f,0.f,0.f);
    float4 a0,a1=z,a2=z,a3=z,a4=z,a5=z,a6=z,a7=z;
    a0 = *(const float4*)(hl + gw*HH);
    int s = g_rowptr[gw], e = g_rowptr[gw+1];
    for (int p = s; p < e; p += 8) {
        const int4* cp = (const int4*)(g_csr + p);  // 8 int2 entries
        int4 c0 = cp[0], c1 = cp[1], c2 = cp[2], c3 = cp[3];
        float4 b0 = *(const float4*)(hl + c0.x*HH);
        float4 b1 = *(const float4*)(hl + c0.z*HH);
        float4 b2 = *(const float4*)(hl + c1.x*HH);
        float4 b3 = *(const float4*)(hl + c1.z*HH);
        float4 b4 = *(const float4*)(hl + c2.x*HH);
        float4 b5 = *(const float4*)(hl + c2.z*HH);
        float4 b6 = *(const float4*)(hl + c3.x*HH);
        float4 b7 = *(const float4*)(hl + c3.z*HH);
        F4ACC(a0,b0); F4ACC(a1,b1); F4ACC(a2,b2); F4ACC(a3,b3);
        F4ACC(a4,b4); F4ACC(a5,b5); F4ACC(a6,b6); F4ACC(a7,b7);
    }
    F4ACC(a0,a1); F4ACC(a2,a3); F4ACC(a4,a5); F4ACC(a6,a7);
    F4ACC(a0,a2); F4ACC(a4,a6); F4ACC(a0,a4);
    *(float4*)(g_hB + gw*HH + lane*4) = a0;
}

// ---------------- GEMM: hout = [relu](X @ M + D/bias) -> g_hA ----------------
// persistent: grid GEMM_GRID x 256 thr, M in dynamic smem (64KB), 32-row tiles
// DOUBLE-BUFFERED X staging: next tile's X prefetched to regs during current FMA
// thread = 4 rows x 4 cols; X rows broadcast within warp; dynamic tile scheduling
template<bool PROJ>
__global__ void __launch_bounds__(256, 2)
gemm_kernel(const float* __restrict__ xin, const float* __restrict__ Mext,
            const float* __restrict__ bias, int which, int slot)
{
    extern __shared__ float smem[];
    float* Ms  = smem;               // [128][128]
    float* Xs0 = smem + HH*HH;       // [32][128]
    float* Xs1 = Xs0 + 32*HH;        // [32][128]
    __shared__ int s_nb[2];          // double-buffered next-tile ids

    const float* M = PROJ ? Mext : (which ? g_M2 : g_M1);
    const float* X = PROJ ? xin  : g_hB;
    const float* D = which ? g_D2 : g_D1;
    float* hout = g_hA;

    int tid = threadIdx.x;
    for (int i = tid; i < HH*HH/4; i += 256)
        ((float4*)Ms)[i] = ((const float4*)M)[i];

    int tx = tid & 31, ty = tid >> 5;   // tx: col group (4 cols), ty: 0..7 (4 rows each)
    int colb = tx * 4;
    int rb = ty * 4;
    int ldidx_r = tid >> 5, ldidx_c = tid & 31;   // staging coords (4 slots/thread)
    float4 zero = make_float4(0.f,0.f,0.f,0.f);

    float4 cbias = zero;
    if (PROJ) cbias = *(const float4*)(bias + colb);

    // ---- prologue: fetch first tile, stage into Xs0
    if (tid == 0) s_nb[0] = atomicAdd(&g_ctr[slot], 1);
    __syncthreads();                 // M + s_nb[0] ready
    int tile = s_nb[0];
    if (tile < NT32) {
        int row0 = tile * 32;
        #pragma unroll
        for (int i = 0; i < 4; i++) {
            int rr = ldidx_r + 8*i, gi = row0 + rr;
            ((float4*)Xs0)[rr*32 + ldidx_c] =
                (gi < NN) ? *(const float4*)(X + gi*HH + ldidx_c*4) : zero;
        }
    }
    if (tid == 0) s_nb[1] = atomicAdd(&g_ctr[slot], 1);
    __syncthreads();                 // Xs0 + s_nb[1] ready

    int cur = 0;
    while (tile < NT32) {
        int ntile = s_nb[cur ^ 1];   // fetched during previous iteration
        int row0 = tile * 32;
        float* Xc = cur ? Xs1 : Xs0;
        float* Xn = cur ? Xs0 : Xs1;

        // prefetch next tile's X into registers (latency hidden by FMA loop)
        float4 st[4];
        if (ntile < NT32) {
            int nrow0 = ntile * 32;
            #pragma unroll
            for (int i = 0; i < 4; i++) {
                int rr = ldidx_r + 8*i, gi = nrow0 + rr;
                st[i] = (gi < NN) ? *(const float4*)(X + gi*HH + ldidx_c*4) : zero;
            }
        }
        // fetch next-next tile id into the slot whose value everyone already consumed
        if (tid == 0) s_nb[cur] = atomicAdd(&g_ctr[slot], 1);

        // acc init from D / bias
        float4 acc[4];
        if (PROJ) {
            #pragma unroll
            for (int r=0;r<4;r++) acc[r] = cbias;
        } else {
            #pragma unroll
            for (int r=0;r<4;r++) {
                int gi = row0 + rb + r;
                acc[r] = (gi < NN) ? *(const float4*)(D + gi*HH + colb) : zero;
            }
        }

        // FMA loop over current tile
        const float* G = Xc + rb*HH;
        #pragma unroll 4
        for (int k0 = 0; k0 < HH; k0 += 4) {
            float4 g0 = *(const float4*)(G + 0*HH + k0);
            float4 g1 = *(const float4*)(G + 1*HH + k0);
            float4 g2 = *(const float4*)(G + 2*HH + k0);
            float4 g3 = *(const float4*)(G + 3*HH + k0);
            float4 m0 = *(const float4*)(Ms + (k0+0)*HH + colb);
            float4 m1 = *(const float4*)(Ms + (k0+1)*HH + colb);
            float4 m2 = *(const float4*)(Ms + (k0+2)*HH + colb);
            float4 m3 = *(const float4*)(Ms + (k0+3)*HH + colb);
            F4FMA(acc[0], g0.x, m0); F4FMA(acc[0], g0.y, m1);
            F4FMA(acc[0], g0.z, m2); F4FMA(acc[0], g0.w, m3);
            F4FMA(acc[1], g1.x, m0); F4FMA(acc[1], g1.y, m1);
            F4FMA(acc[1], g1.z, m2); F4FMA(acc[1], g1.w, m3);
            F4FMA(acc[2], g2.x, m0); F4FMA(acc[2], g2.y, m1);
            F4FMA(acc[2], g2.z, m2); F4FMA(acc[2], g2.w, m3);
            F4FMA(acc[3], g3.x, m0); F4FMA(acc[3], g3.y, m1);
            F4FMA(acc[3], g3.z, m2); F4FMA(acc[3], g3.w, m3);
        }

        // write output
        #pragma unroll
        for (int r=0;r<4;r++) {
            int gi = row0 + rb + r;
            if (gi < NN) {
                float4 o = acc[r];
                if (!PROJ) {
                    o.x=fmaxf(o.x,0.f); o.y=fmaxf(o.y,0.f);
                    o.z=fmaxf(o.z,0.f); o.w=fmaxf(o.w,0.f);
                }
                *(float4*)(hout + gi*HH + colb) = o;
            }
        }

        // commit prefetched X into the alternate buffer
        if (ntile < NT32) {
            #pragma unroll
            for (int i = 0; i < 4; i++) {
                int rr = ldidx_r + 8*i;
                ((float4*)Xn)[rr*32 + ldidx_c] = st[i];
            }
        }
        __syncthreads();   // Xn staged for all; everyone done reading Xc; s_nb[cur] visible
        cur ^= 1;
        tile = ntile;
    }
}

// ---------------- pooling (batch sorted -> run-based partial reduce) ----------------
__global__ void pool_kernel(const int* __restrict__ batch) {
    __shared__ int bsh[128];
    int c = threadIdx.x;
    int s = blockIdx.x*128;
    int nloc = NN - s; if (nloc > 128) nloc = 128;
    for (int i=c; i<nloc; i+=128) bsh[i] = batch[s+i];
    __syncthreads();
    const float* h = g_hA;
    float sum=0.f, mx=0.f; int cnt=0;
    int cur = bsh[0];
    for (int i=0;i<nloc;i++) {
        int g = bsh[i];
        if (g != cur) {
            atomicAdd(&g_psum[cur*HH+c], sum);
            atomicMax((unsigned int*)&g_pmax[cur*HH+c], __float_as_uint(mx));
            if (c==0) atomicAdd(&g_cnt[cur], cnt);
            cur=g; sum=0.f; mx=0.f; cnt=0;
        }
        float v = h[(s+i)*HH + c];
        sum += v; mx = fmaxf(mx, v); cnt++;
    }
    atomicAdd(&g_psum[cur*HH+c], sum);
    atomicMax((unsigned int*)&g_pmax[cur*HH+c], __float_as_uint(mx));
    if (c==0) atomicAdd(&g_cnt[cur], cnt);
}

// ---------------- readout head ----------------
__global__ void head_kernel(const float* __restrict__ Wm1, const float* __restrict__ bm1,
                            const float* __restrict__ Wm2, const float* __restrict__ bm2,
                            float* __restrict__ out) {
    __shared__ float pooled[2*HH];
    __shared__ float z1[HH];
    int g = blockIdx.x, c = threadIdx.x;
    float denom = fmaxf((float)g_cnt[g], 1.f);
    pooled[c]    = g_psum[g*HH+c] / denom;
    pooled[HH+c] = g_pmax[g*HH+c];
    __syncthreads();
    float a = bm1[c];
    #pragma unroll 8
    for (int k=0;k<2*HH;k++) a += pooled[k]*Wm1[k*HH+c];
    z1[c] = fmaxf(a, 0.f);
    __syncthreads();
    if (c < 2) {
        float o = bm2[c];
        for (int k=0;k<HH;k++) o += z1[k]*Wm2[k*2+c];
        out[g*2+c] = 1.f/(1.f+expf(-o));
    }
}

// ---------------- launch ----------------
extern "C" void kernel_launch(void* const* d_in, const int* in_sizes, int n_in,
                              void* d_out, int out_size) {
    const float* x         = (const float*)d_in[0];
    const float* edge_attr = (const float*)d_in[1];
    const int*   ei        = (const int*)  d_in[2];
    const int*   batch     = (const int*)  d_in[3];
    const float* Wn2l = (const float*)d_in[4];
    const float* bn2l = (const float*)d_in[5];
    const float* We2l = (const float*)d_in[6];
    const float* be2l = (const float*)d_in[7];
    const float* Wn1  = (const float*)d_in[8];
    const float* bn1  = (const float*)d_in[9];
    const float* We1  = (const float*)d_in[10];
    const float* be1  = (const float*)d_in[11];
    const float* Wu1  = (const float*)d_in[12];
    const float* bu1  = (const float*)d_in[13];
    const float* Wn2  = (const float*)d_in[14];
    const float* bn2  = (const float*)d_in[15];
    const float* We2  = (const float*)d_in[16];
    const float* be2  = (const float*)d_in[17];
    const float* Wu2  = (const float*)d_in[18];
    const float* bu2  = (const float*)d_in[19];
    const float* Wm1  = (const float*)d_in[20];
    const float* bm1  = (const float*)d_in[21];
    const float* Wm2  = (const float*)d_in[22];
    const float* bm2  = (const float*)d_in[23];
    float* out = (float*)d_out;

    const int* src = ei;
    const int* dst = ei + EE;

    cudaFuncSetAttribute(gemm_kernel<true>,  cudaFuncAttributeMaxDynamicSharedMemorySize, GEMM_SMEM);
    cudaFuncSetAttribute(gemm_kernel<false>, cudaFuncAttributeMaxDynamicSharedMemorySize, GEMM_SMEM);

    init_zero<<<160, 256>>>();
    deg_kernel<<<(EE+255)/256, 256>>>(dst);
    scan1_kernel<<<NSB, 256>>>();
    // h0 = x @ Wn2l + bn2l -> g_hA (independent of CSR), slot 0
    gemm_kernel<true><<<GEMM_GRID, 256, GEMM_SMEM>>>(x, Wn2l, bn2l, 0, 0);
    scan2_kernel<<<1, 128>>>();
    scan3_kernel<<<NSB, 256>>>();
    fill_kernel<<<(EE+255)/256, 256>>>(src, dst);
    pad_kernel<<<(NN+255)/256, 256>>>();
    S_kernel<<<(NN*32)/256, 256>>>(edge_attr);

    tinyA<<<161, 128>>>(Wn1, Wu1, We1, We2l, be2l, be1, bn1, 0);
    tinyA<<<161, 128>>>(Wn2, Wu2, We2, We2l, be2l, be2, bn2, 1);
    tinyB<<<34, 128>>>(Wu1, bn1, be1, bu1, 0);
    tinyB<<<34, 128>>>(Wu2, bn2, be2, bu2, 1);
    D_kernel<<<296, 128>>>();

    // 3 x (conv1, conv2): agg (hA->hB) then gemm (hB->hA); slots 1..6
    int slot = 1;
    for (int l = 0; l < 3; l++) {
        agg_kernel<<<(NN*32+255)/256, 256>>>();
        gemm_kernel<false><<<GEMM_GRID, 256, GEMM_SMEM>>>(nullptr, nullptr, nullptr, 0, slot++);
        agg_kernel<<<(NN*32+255)/256, 256>>>();
        gemm_kernel<false><<<GEMM_GRID, 256, GEMM_SMEM>>>(nullptr, nullptr, nullptr, 1, slot++);
    }

    pool_kernel<<<(NN+127)/128, 128>>>(batch);
    head_kernel<<<GGR, 128>>>(Wm1, bm1, Wm2, bm2, out);
}

// round 17
// speedup vs baseline: 1.1586x; 1.0394x over previous
#include <cuda_runtime.h>
#include <math.h>

#define NN 20000
#define EE 640000
#define EPAD 800000        // CSR capacity, rows padded to multiples of 8
#define GGR 64
#define HH 128
#define EIN 32
#define NSB ((NN + 255) / 256) // 79 scan blocks
#define NT32 ((NN + 31) / 32)  // 625 gemm row tiles
#define GEMM_GRID 592           // 296 blocks per column-half
#define GEMM_SMEM ((HH*64 + 32*HH)*4)   // 32KB M-half + 16KB X = 48KB dynamic

// ---------------- scratch (static device globals; no allocation) ----------------
__device__ float g_hA[(NN+1)*HH];   // h lives here; row NN = zero sentinel
__device__ float g_hB[NN*HH];       // X = (A+I)h scratch
__device__ float g_D1[NN*HH];
__device__ float g_D2[NN*HH];
__device__ float g_S[NN*EIN];
__device__ int   g_deg[NN];
__device__ int   g_rowptr[NN+1];    // padded exclusive scan
__device__ int   g_fill[NN];
__device__ int2  g_csr[EPAD];       // .x = src node (NN = sentinel), .y = edge id
__device__ int   g_tmp[NN];
__device__ int   g_bsum[NSB];
__device__ int   g_boff[NSB];
__device__ int   g_ctr[16];         // dynamic tile counters (2 per gemm launch)
__device__ float g_M1[HH*HH], g_M2[HH*HH];
__device__ float g_T1[EIN*HH], g_T2[EIN*HH];
__device__ float g_Gm1[EIN*HH], g_Gm2[EIN*HH];
__device__ float g_w1[HH], g_w2[HH];
__device__ float g_u1[HH], g_u2[HH];
__device__ float g_v1[HH], g_v2[HH];
__device__ float g_psum[GGR*HH];
__device__ float g_pmax[GGR*HH];
__device__ int   g_cnt[GGR];

#define F4ACC(a,b) { (a).x+=(b).x; (a).y+=(b).y; (a).z+=(b).z; (a).w+=(b).w; }
#define F4FMA(a,s,m) { (a).x+=(s)*(m).x; (a).y+=(s)*(m).y; (a).z+=(s)*(m).z; (a).w+=(s)*(m).w; }

// ---------------- init ----------------
__global__ void init_zero() {
    int i = blockIdx.x*blockDim.x + threadIdx.x;
    int stride = gridDim.x*blockDim.x;
    for (int k=i; k<NN; k+=stride) g_deg[k]=0;
    for (int k=i; k<GGR*HH; k+=stride){ g_psum[k]=0.f; g_pmax[k]=0.f; }
    for (int k=i; k<GGR; k+=stride) g_cnt[k]=0;
    for (int k=i; k<HH; k+=stride) g_hA[NN*HH+k]=0.f;
    if (i < 16) g_ctr[i] = 0;
}

// ---------------- CSR build ----------------
__global__ void deg_kernel(const int* __restrict__ dst) {
    int e = blockIdx.x*blockDim.x + threadIdx.x;
    if (e < EE) atomicAdd(&g_deg[dst[e]], 1);
}

// 3-phase scan of padded degrees
__global__ void scan1_kernel() {
    __shared__ int ws[8];
    int b = blockIdx.x, t = threadIdx.x;
    int i = b*256 + t;
    int v = (i < NN) ? ((g_deg[i] + 7) & ~7) : 0;
    int x = v;
    #pragma unroll
    for (int o=1;o<32;o<<=1){ int y=__shfl_up_sync(0xFFFFFFFFu,x,o); if ((t&31)>=o) x+=y; }
    if ((t&31)==31) ws[t>>5]=x;
    __syncthreads();
    if (t < 8) {
        int s = ws[t];
        #pragma unroll
        for (int o=1;o<8;o<<=1){ int y=__shfl_up_sync(0xFFu,s,o); if (t>=o) s+=y; }
        ws[t] = s;
    }
    __syncthreads();
    int add = (t>=32) ? ws[(t>>5)-1] : 0;
    int incl = x + add;
    if (i < NN) g_tmp[i] = incl;
    if (t == 255) g_bsum[b] = incl;
}

__global__ void scan2_kernel() {
    __shared__ int ws[4];
    int t = threadIdx.x;
    int v = (t < NSB) ? g_bsum[t] : 0;
    int x = v;
    #pragma unroll
    for (int o=1;o<32;o<<=1){ int y=__shfl_up_sync(0xFFFFFFFFu,x,o); if ((t&31)>=o) x+=y; }
    if ((t&31)==31) ws[t>>5]=x;
    __syncthreads();
    int add = 0;
    if (t>=32) add = ws[0];
    if (t>=64) add += ws[1];
    if (t>=96) add += ws[2];
    if (t < NSB) g_boff[t] = x + add - v;
}

// scan3 also pre-pads each row's padding region with sentinel entries
__global__ void scan3_kernel() {
    int i = blockIdx.x*256 + threadIdx.x;
    if (i < NN) {
        int d = g_deg[i];
        int v = (d + 7) & ~7;
        int excl = g_boff[blockIdx.x] + g_tmp[i] - v;
        g_rowptr[i] = excl;
        g_fill[i]   = excl;
        if (i == NN-1) g_rowptr[NN] = excl + v;
        int2 s = make_int2(NN, 0);
        for (int p = excl + d; p < excl + v; p++) g_csr[p] = s;
    }
}

__global__ void fill_kernel(const int* __restrict__ src, const int* __restrict__ dst) {
    int e = blockIdx.x*blockDim.x + threadIdx.x;
    if (e < EE) {
        int d = dst[e];
        int pos = atomicAdd(&g_fill[d], 1);
        g_csr[pos] = make_int2(src[e], e);
    }
}

// S[i,:] = sum of edge_attr over real incoming edges (warp per node, lane = channel)
__global__ void S_kernel(const float* __restrict__ edge_attr) {
    int gw   = (blockIdx.x*blockDim.x + threadIdx.x) >> 5;
    int lane = threadIdx.x & 31;
    if (gw >= NN) return;
    int s = g_rowptr[gw], d = g_deg[gw];
    float a0=0.f, a1=0.f, a2=0.f, a3=0.f;
    int p = s;
    for (; p + 4 <= s + d; p += 4) {
        int e0 = g_csr[p].y, e1 = g_csr[p+1].y, e2 = g_csr[p+2].y, e3 = g_csr[p+3].y;
        a0 += edge_attr[e0*EIN + lane];
        a1 += edge_attr[e1*EIN + lane];
        a2 += edge_attr[e2*EIN + lane];
        a3 += edge_attr[e3*EIN + lane];
    }
    for (; p < s + d; p++) a0 += edge_attr[g_csr[p].y*EIN + lane];
    g_S[gw*EIN + lane] = (a0+a1)+(a2+a3);
}

// ---------------- tiny weight-product precompute ----------------
__global__ void tinyA(const float* __restrict__ Wn, const float* __restrict__ Wu,
                      const float* __restrict__ We, const float* __restrict__ We2l,
                      const float* __restrict__ be2l, const float* __restrict__ be,
                      const float* __restrict__ bn, int X) {
    int c = threadIdx.x, b = blockIdx.x;
    float* M = X ? g_M2 : g_M1;
    float* T = X ? g_T2 : g_T1;
    float* w = X ? g_w2 : g_w1;
    if (b < 128) {
        float a = 0.f;
        #pragma unroll 8
        for (int k=0;k<128;k++) a += Wn[b*128+k]*Wu[k*128+c];
        M[b*128+c] = a;
    } else if (b < 160) {
        int r = b - 128;
        float a = 0.f;
        #pragma unroll 8
        for (int k=0;k<128;k++) a += We2l[r*128+k]*We[k*128+c];
        T[r*128+c] = a;
    } else {
        float a = be[c] + bn[c];
        #pragma unroll 8
        for (int k=0;k<128;k++) a += be2l[k]*We[k*128+c];
        w[c] = a;
    }
}

__global__ void tinyB(const float* __restrict__ Wu, const float* __restrict__ bn,
                      const float* __restrict__ be, const float* __restrict__ bu, int X) {
    int c = threadIdx.x, b = blockIdx.x;
    const float* T = X ? g_T2 : g_T1;
    const float* w = X ? g_w2 : g_w1;
    float* Gm = X ? g_Gm2 : g_Gm1;
    float* u  = X ? g_u2  : g_u1;
    float* v  = X ? g_v2  : g_v1;
    if (b < 32) {
        float a = 0.f;
        #pragma unroll 8
        for (int k=0;k<128;k++) a += T[b*128+k]*Wu[k*128+c];
        Gm[b*128+c] = a;
    } else if (b == 32) {
        float a = 0.f;
        #pragma unroll 8
        for (int k=0;k<128;k++) a += w[k]*Wu[k*128+c];
        u[c] = a;
    } else {
        float a = bu[c];
        #pragma unroll 8
        for (int k=0;k<128;k++) a += (bn[k]+be[k])*Wu[k*128+c];
        v[c] = a;
    }
}

// D_X[i,:] = S[i,:] @ G_X + deg[i]*u_X + v_X
__global__ void D_kernel() {
    __shared__ float G1s[EIN*HH];
    __shared__ float G2s[EIN*HH];
    __shared__ float Ssh[EIN];
    int c = threadIdx.x;
    for (int k=c; k<EIN*HH; k+=128) { G1s[k]=g_Gm1[k]; G2s[k]=g_Gm2[k]; }
    float u1=g_u1[c], u2=g_u2[c], v1=g_v1[c], v2=g_v2[c];
    __syncthreads();
    for (int i=blockIdx.x; i<NN; i+=gridDim.x) {
        if (c<EIN) Ssh[c] = g_S[i*EIN+c];
        __syncthreads();
        float dg = (float)g_deg[i];
        float a1 = v1 + dg*u1, a2 = v2 + dg*u2;
        #pragma unroll
        for (int k=0;k<EIN;k++){ float s=Ssh[k]; a1 += s*G1s[k*HH+c]; a2 += s*G2s[k*HH+c]; }
        g_D1[i*HH+c] = a1;
        g_D2[i*HH+c] = a2;
        __syncthreads();
    }
}

// ---------------- aggregation: X = (A+I) h  (g_hA -> g_hB) ----------------
// warp per node, lane owns 4 channels, MLP-8 over padded CSR (int2 entries)
__global__ void agg_kernel() {
    int gw   = (blockIdx.x*blockDim.x + threadIdx.x) >> 5;
    int lane = threadIdx.x & 31;
    if (gw >= NN) return;
    const float* hl = g_hA + lane*4;
    float4 z = make_float4(0.f,0.f,0.f,0.f);
    float4 a0,a1=z,a2=z,a3=z,a4=z,a5=z,a6=z,a7=z;
    a0 = *(const float4*)(hl + gw*HH);
    int s = g_rowptr[gw], e = g_rowptr[gw+1];
    for (int p = s; p < e; p += 8) {
        const int4* cp = (const int4*)(g_csr + p);  // 8 int2 entries
        int4 c0 = cp[0], c1 = cp[1], c2 = cp[2], c3 = cp[3];
        float4 b0 = *(const float4*)(hl + c0.x*HH);
        float4 b1 = *(const float4*)(hl + c0.z*HH);
        float4 b2 = *(const float4*)(hl + c1.x*HH);
        float4 b3 = *(const float4*)(hl + c1.z*HH);
        float4 b4 = *(const float4*)(hl + c2.x*HH);
        float4 b5 = *(const float4*)(hl + c2.z*HH);
        float4 b6 = *(const float4*)(hl + c3.x*HH);
        float4 b7 = *(const float4*)(hl + c3.z*HH);
        F4ACC(a0,b0); F4ACC(a1,b1); F4ACC(a2,b2); F4ACC(a3,b3);
        F4ACC(a4,b4); F4ACC(a5,b5); F4ACC(a6,b6); F4ACC(a7,b7);
    }
    F4ACC(a0,a1); F4ACC(a2,a3); F4ACC(a4,a5); F4ACC(a6,a7);
    F4ACC(a0,a2); F4ACC(a4,a6); F4ACC(a0,a4);
    *(float4*)(g_hB + gw*HH + lane*4) = a0;
}

// ---------------- GEMM: hout = [relu](X @ M + D/bias) -> g_hA ----------------
// COLUMN-SPLIT persistent GEMM: 592 blocks x 128 thr, 4 blocks/SM.
// Block parity selects a 64-column half of M (32KB smem); 32-row X tiles (16KB).
// Each half-group (296 blocks) schedules the 625 row tiles via its own counter.
// thread = 4 rows x 4 cols; X rows broadcast within warp.
template<bool PROJ>
__global__ void __launch_bounds__(128, 4)
gemm_kernel(const float* __restrict__ xin, const float* __restrict__ Mext,
            const float* __restrict__ bias, int which, int slot)
{
    extern __shared__ float smem[];
    float* Ms = smem;              // [128][64]  column half
    float* Xs = smem + HH*64;      // [32][128]
    __shared__ int s_tile;

    const float* M = PROJ ? Mext : (which ? g_M2 : g_M1);
    const float* X = PROJ ? xin  : g_hB;
    const float* D = which ? g_D2 : g_D1;
    float* hout = g_hA;

    int tid = threadIdx.x;
    int half = blockIdx.x & 1;
    int colbase = half * 64;
    int ctr = slot*2 + half;

    // stage M half: 128 rows x 64 cols = 2048 float4, 16 per thread
    for (int i = tid; i < HH*64/4; i += 128) {
        int row = i >> 4, c4 = i & 15;
        ((float4*)Ms)[i] = ((const float4*)(M + row*HH + colbase))[c4];
    }

    int tx = tid & 15, ty = tid >> 4;   // tx: col group (4 of 64), ty: 0..7 (4 rows each)
    int colb = tx * 4;
    int rb = ty * 4;
    float4 zero = make_float4(0.f,0.f,0.f,0.f);

    float4 cbias = zero;
    if (PROJ) cbias = *(const float4*)(bias + colbase + colb);

    for (;;) {
        __syncthreads();     // protect prev-iter Xs reads + s_tile (also first-pass Ms)
        if (tid == 0) s_tile = atomicAdd(&g_ctr[ctr], 1);
        __syncthreads();
        int tile = s_tile;
        if (tile >= NT32) break;
        int row0 = tile * 32;

        // stage X tile: 32 rows x 128 cols = 1024 float4, 8 per thread
        #pragma unroll
        for (int i = 0; i < 8; i++) {
            int idx = tid + 128*i;
            int rr = idx >> 5, cc = idx & 31;
            int gi = row0 + rr;
            ((float4*)Xs)[idx] = (gi < NN) ? *(const float4*)(X + gi*HH + cc*4) : zero;
        }
        // acc init from D / bias (global, overlaps staging)
        float4 acc[4];
        if (PROJ) {
            #pragma unroll
            for (int r=0;r<4;r++) acc[r] = cbias;
        } else {
            #pragma unroll
            for (int r=0;r<4;r++) {
                int gi = row0 + rb + r;
                acc[r] = (gi < NN) ? *(const float4*)(D + gi*HH + colbase + colb) : zero;
            }
        }
        __syncthreads();

        const float* G = Xs + rb*HH;
        #pragma unroll 4
        for (int k0 = 0; k0 < HH; k0 += 4) {
            float4 g0 = *(const float4*)(G + 0*HH + k0);
            float4 g1 = *(const float4*)(G + 1*HH + k0);
            float4 g2 = *(const float4*)(G + 2*HH + k0);
            float4 g3 = *(const float4*)(G + 3*HH + k0);
            float4 m0 = *(const float4*)(Ms + (k0+0)*64 + colb);
            float4 m1 = *(const float4*)(Ms + (k0+1)*64 + colb);
            float4 m2 = *(const float4*)(Ms + (k0+2)*64 + colb);
            float4 m3 = *(const float4*)(Ms + (k0+3)*64 + colb);
            F4FMA(acc[0], g0.x, m0); F4FMA(acc[0], g0.y, m1);
            F4FMA(acc[0], g0.z, m2); F4FMA(acc[0], g0.w, m3);
            F4FMA(acc[1], g1.x, m0); F4FMA(acc[1], g1.y, m1);
            F4FMA(acc[1], g1.z, m2); F4FMA(acc[1], g1.w, m3);
            F4FMA(acc[2], g2.x, m0); F4FMA(acc[2], g2.y, m1);
            F4FMA(acc[2], g2.z, m2); F4FMA(acc[2], g2.w, m3);
            F4FMA(acc[3], g3.x, m0); F4FMA(acc[3], g3.y, m1);
            F4FMA(acc[3], g3.z, m2); F4FMA(acc[3], g3.w, m3);
        }
        #pragma unroll
        for (int r=0;r<4;r++) {
            int gi = row0 + rb + r;
            if (gi < NN) {
                float4 o = acc[r];
                if (!PROJ) {
                    o.x=fmaxf(o.x,0.f); o.y=fmaxf(o.y,0.f);
                    o.z=fmaxf(o.z,0.f); o.w=fmaxf(o.w,0.f);
                }
                *(float4*)(hout + gi*HH + colbase + colb) = o;
            }
        }
    }
}

// ---------------- pooling (batch sorted -> run-based partial reduce) ----------------
__global__ void pool_kernel(const int* __restrict__ batch) {
    __shared__ int bsh[128];
    int c = threadIdx.x;
    int s = blockIdx.x*128;
    int nloc = NN - s; if (nloc > 128) nloc = 128;
    for (int i=c; i<nloc; i+=128) bsh[i] = batch[s+i];
    __syncthreads();
    const float* h = g_hA;
    float sum=0.f, mx=0.f; int cnt=0;
    int cur = bsh[0];
    for (int i=0;i<nloc;i++) {
        int g = bsh[i];
        if (g != cur) {
            atomicAdd(&g_psum[cur*HH+c], sum);
            atomicMax((unsigned int*)&g_pmax[cur*HH+c], __float_as_uint(mx));
            if (c==0) atomicAdd(&g_cnt[cur], cnt);
            cur=g; sum=0.f; mx=0.f; cnt=0;
        }
        float v = h[(s+i)*HH + c];
        sum += v; mx = fmaxf(mx, v); cnt++;
    }
    atomicAdd(&g_psum[cur*HH+c], sum);
    atomicMax((unsigned int*)&g_pmax[cur*HH+c], __float_as_uint(mx));
    if (c==0) atomicAdd(&g_cnt[cur], cnt);
}

// ---------------- readout head ----------------
__global__ void head_kernel(const float* __restrict__ Wm1, const float* __restrict__ bm1,
                            const float* __restrict__ Wm2, const float* __restrict__ bm2,
                            float* __restrict__ out) {
    __shared__ float pooled[2*HH];
    __shared__ float z1[HH];
    int g = blockIdx.x, c = threadIdx.x;
    float denom = fmaxf((float)g_cnt[g], 1.f);
    pooled[c]    = g_psum[g*HH+c] / denom;
    pooled[HH+c] = g_pmax[g*HH+c];
    __syncthreads();
    float a = bm1[c];
    #pragma unroll 8
    for (int k=0;k<2*HH;k++) a += pooled[k]*Wm1[k*HH+c];
    z1[c] = fmaxf(a, 0.f);
    __syncthreads();
    if (c < 2) {
        float o = bm2[c];
        for (int k=0;k<HH;k++) o += z1[k]*Wm2[k*2+c];
        out[g*2+c] = 1.f/(1.f+expf(-o));
    }
}

// ---------------- launch ----------------
extern "C" void kernel_launch(void* const* d_in, const int* in_sizes, int n_in,
                              void* d_out, int out_size) {
    const float* x         = (const float*)d_in[0];
    const float* edge_attr = (const float*)d_in[1];
    const int*   ei        = (const int*)  d_in[2];
    const int*   batch     = (const int*)  d_in[3];
    const float* Wn2l = (const float*)d_in[4];
    const float* bn2l = (const float*)d_in[5];
    const float* We2l = (const float*)d_in[6];
    const float* be2l = (const float*)d_in[7];
    const float* Wn1  = (const float*)d_in[8];
    const float* bn1  = (const float*)d_in[9];
    const float* We1  = (const float*)d_in[10];
    const float* be1  = (const float*)d_in[11];
    const float* Wu1  = (const float*)d_in[12];
    const float* bu1  = (const float*)d_in[13];
    const float* Wn2  = (const float*)d_in[14];
    const float* bn2  = (const float*)d_in[15];
    const float* We2  = (const float*)d_in[16];
    const float* be2  = (const float*)d_in[17];
    const float* Wu2  = (const float*)d_in[18];
    const float* bu2  = (const float*)d_in[19];
    const float* Wm1  = (const float*)d_in[20];
    const float* bm1  = (const float*)d_in[21];
    const float* Wm2  = (const float*)d_in[22];
    const float* bm2  = (const float*)d_in[23];
    float* out = (float*)d_out;

    const int* src = ei;
    const int* dst = ei + EE;

    cudaFuncSetAttribute(gemm_kernel<true>,  cudaFuncAttributeMaxDynamicSharedMemorySize, GEMM_SMEM);
    cudaFuncSetAttribute(gemm_kernel<false>, cudaFuncAttributeMaxDynamicSharedMemorySize, GEMM_SMEM);

    init_zero<<<160, 256>>>();
    deg_kernel<<<(EE+255)/256, 256>>>(dst);
    scan1_kernel<<<NSB, 256>>>();
    // h0 = x @ Wn2l + bn2l -> g_hA (independent of CSR), slot 0
    gemm_kernel<true><<<GEMM_GRID, 128, GEMM_SMEM>>>(x, Wn2l, bn2l, 0, 0);
    scan2_kernel<<<1, 128>>>();
    scan3_kernel<<<NSB, 256>>>();
    fill_kernel<<<(EE+255)/256, 256>>>(src, dst);
    S_kernel<<<(NN*32)/256, 256>>>(edge_attr);

    tinyA<<<161, 128>>>(Wn1, Wu1, We1, We2l, be2l, be1, bn1, 0);
    tinyA<<<161, 128>>>(Wn2, Wu2, We2, We2l, be2l, be2, bn2, 1);
    tinyB<<<34, 128>>>(Wu1, bn1, be1, bu1, 0);
    tinyB<<<34, 128>>>(Wu2, bn2, be2, bu2, 1);
    D_kernel<<<296, 128>>>();

    // 3 x (conv1, conv2): agg (hA->hB) then gemm (hB->hA); slots 1..6
    int slot = 1;
    for (int l = 0; l < 3; l++) {
        agg_kernel<<<(NN*32+255)/256, 256>>>();
        gemm_kernel<false><<<GEMM_GRID, 128, GEMM_SMEM>>>(nullptr, nullptr, nullptr, 0, slot++);
        agg_kernel<<<(NN*32+255)/256, 256>>>();
        gemm_kernel<false><<<GEMM_GRID, 128, GEMM_SMEM>>>(nullptr, nullptr, nullptr, 1, slot++);
    }

    pool_kernel<<<(NN+127)/128, 128>>>(batch);
    head_kernel<<<GGR, 128>>>(Wm1, bm1, Wm2, bm2, out);
}